// round 7
// baseline (speedup 1.0000x reference)
#include <cuda_runtime.h>
#include <cstdint>

#define LL 2048
#define BB 32
#define HH 1024
#define MM (LL*BB)

// quantization scales
#define SA      (8.0f/127.0f)
#define INV_SA  (127.0f/8.0f)
#define SB      (0.03125f/127.0f)
#define INV_SB  (127.0f/0.03125f)
#define S1      (SA*SB)
#define S2      (SA*SB/256.0f)

// ---------------- device scratch ----------------
__device__ uint8_t g_qa_hi[(size_t)MM*HH];   // enc hi int8, k-permuted rows
__device__ uint8_t g_qa_lo[(size_t)MM*HH];   // enc lo
__device__ uint8_t g_qb_hi[(size_t)HH*HH];   // w1 hi
__device__ uint8_t g_qb_lo[(size_t)HH*HH];   // w1 lo
__device__ float2 g_pstP[(HH/2)*BB];         // (pst[2np][b], pst[2np+1][b]), bias folded
__device__ float g_score[MM];                // scores [l*B+b]
__device__ float g_cpart[32*BB*HH];          // context partials

// ---------------- PTX helpers ----------------
__device__ __forceinline__ uint32_t smem_u32(const void* p){
    uint32_t a;
    asm("{ .reg .u64 t; cvta.to.shared.u64 t, %1; cvt.u32.u64 %0, t; }" : "=r"(a) : "l"(p));
    return a;
}
__device__ __forceinline__ void cp16(uint32_t dst, const void* src){
    asm volatile("cp.async.ca.shared.global [%0], [%1], 16;" :: "r"(dst), "l"(src));
}
__device__ __forceinline__ void cp_commit(){ asm volatile("cp.async.commit_group;" ::: "memory"); }
__device__ __forceinline__ void cp_wait2(){ asm volatile("cp.async.wait_group 2;" ::: "memory"); }
__device__ __forceinline__ void cp_wait0(){ asm volatile("cp.async.wait_group 0;" ::: "memory"); }
__device__ __forceinline__ void imma(int* c, uint32_t a0, uint32_t a1, uint32_t a2, uint32_t a3,
                                     uint32_t b0, uint32_t b1){
    asm volatile("mma.sync.aligned.m16n8k32.row.col.s32.s8.s8.s32 "
        "{%0,%1,%2,%3}, {%4,%5,%6,%7}, {%8,%9}, {%0,%1,%2,%3};"
        : "+r"(c[0]), "+r"(c[1]), "+r"(c[2]), "+r"(c[3])
        : "r"(a0), "r"(a1), "r"(a2), "r"(a3), "r"(b0), "r"(b1));
}
// pair tanh via f16x2 MUFU
__device__ __forceinline__ float2 tanh2(float x0, float x1){
    uint32_t h2, t2;
    asm("cvt.rn.f16x2.f32 %0, %1, %2;" : "=r"(h2) : "f"(x1), "f"(x0));
    asm("tanh.approx.f16x2 %0, %1;" : "=r"(t2) : "r"(h2));
    float r0, r1;
    asm("{.reg .b16 l, h;\n mov.b32 {l, h}, %2;\n cvt.f32.f16 %0, l;\n cvt.f32.f16 %1, h;}"
        : "=f"(r0), "=f"(r1) : "r"(t2));
    return make_float2(r0, r1);
}

// ---------------- SMEM layout ----------------
// stage: A_hi 128x32B | A_lo | B_hi 64x32B | B_lo  = 12288 B; 4 stages
#define STAGE_SZ 12288
#define OALO     4096
#define OBHI     8192
#define OBLO     10240
#define O_RED    49152
#define SMEM_BYTES 57856      // 4*12288 + 128*17*4

// ---------------------------------------------------------------------------
// quantize: x ~ s*(qh + ql/256). Writes hi/lo bytes in k-permuted layout:
// within each k32 window, stored byte p=8q+i <- orig k=4q+i, p=8q+4+i <- k=16+4q+i.
// One thread per (row, window w, quad q): reads 2 float4, writes uint2 hi + uint2 lo.
// ---------------------------------------------------------------------------
__device__ __forceinline__ void q2(float x, float inv_s, int& qh, int& ql){
    float xs = x * inv_s;
    float qhf = rintf(fminf(fmaxf(xs, -127.f), 127.f));
    float r = (xs - qhf) * 256.f;
    qh = (int)qhf;
    ql = (int)rintf(fminf(fmaxf(r, -128.f), 127.f));
}
__device__ __forceinline__ uint32_t pack4(int b0, int b1, int b2, int b3){
    return (uint32_t)(b0 & 255) | ((uint32_t)(b1 & 255) << 8) |
           ((uint32_t)(b2 & 255) << 16) | ((uint32_t)(b3 & 255) << 24);
}
__global__ void quant_kernel(const float* __restrict__ src, uint8_t* __restrict__ dhi,
                             uint8_t* __restrict__ dlo, float inv_s){
    int idx = blockIdx.x * 256 + threadIdx.x;    // rows*128 threads
    int q = idx & 3, w = (idx >> 2) & 31;
    int m = idx >> 7;
    const float* p = src + (size_t)m*HH + w*32 + q*4;
    float4 x0 = *(const float4*)p;
    float4 x1 = *(const float4*)(p + 4);         // +16 floats? no: k=16+4q -> p+16-? 
    // careful: orig k = 16+4q -> offset (16+4q)-(4q) = 16 floats from row base, i.e. +16 from (w*32+q*4)? 
    x1 = *(const float4*)(src + (size_t)m*HH + w*32 + 16 + q*4);
    int h[8], l[8];
    q2(x0.x, inv_s, h[0], l[0]); q2(x0.y, inv_s, h[1], l[1]);
    q2(x0.z, inv_s, h[2], l[2]); q2(x0.w, inv_s, h[3], l[3]);
    q2(x1.x, inv_s, h[4], l[4]); q2(x1.y, inv_s, h[5], l[5]);
    q2(x1.z, inv_s, h[6], l[6]); q2(x1.w, inv_s, h[7], l[7]);
    size_t off = (size_t)m*HH + w*32 + q*8;
    *(uint2*)(dhi + off) = make_uint2(pack4(h[0],h[1],h[2],h[3]), pack4(h[4],h[5],h[6],h[7]));
    *(uint2*)(dlo + off) = make_uint2(pack4(l[0],l[1],l[2],l[3]), pack4(l[4],l[5],l[6],l[7]));
}

// ---------------------------------------------------------------------------
// pstP[np*32+b] = (pst[2np][b], pst[2np+1][b]); exact fp32
// ---------------------------------------------------------------------------
__global__ void pstT_kernel(const float* __restrict__ state, const float* __restrict__ w2,
                            const float* __restrict__ w1b, const float* __restrict__ w2b){
    int gw = (blockIdx.x * blockDim.x + threadIdx.x) >> 5;
    int lane = threadIdx.x & 31;
    if (gw >= (HH/2)*(BB/2)) return;
    int np = gw >> 4;
    int b0 = (gw & 15) * 2;
    int n0 = np * 2;
    const float* w0 = w2 + (size_t)n0 * HH;
    const float* w1r = w2 + (size_t)(n0+1) * HH;
    const float* s0 = state + b0*HH;
    const float* s1 = state + (b0+1)*HH;
    float a00=0.f, a01=0.f, a10=0.f, a11=0.f;
    #pragma unroll 4
    for (int h = lane; h < HH; h += 32){
        float x0 = s0[h], x1 = s1[h];
        float u = w0[h], w = w1r[h];
        a00 += u*x0; a01 += u*x1;
        a10 += w*x0; a11 += w*x1;
    }
    #pragma unroll
    for (int o = 16; o; o >>= 1){
        a00 += __shfl_xor_sync(~0u, a00, o);
        a01 += __shfl_xor_sync(~0u, a01, o);
        a10 += __shfl_xor_sync(~0u, a10, o);
        a11 += __shfl_xor_sync(~0u, a11, o);
    }
    if (lane == 0){
        float bias0 = w1b[n0] + w2b[n0];
        float bias1 = w1b[n0+1] + w2b[n0+1];
        g_pstP[np*BB + b0]   = make_float2(a00 + bias0, a10 + bias1);
        g_pstP[np*BB + b0+1] = make_float2(a01 + bias0, a11 + bias1);
    }
}

// ---------------------------------------------------------------------------
// cp.async one stage: A 128x32B (hi+lo) + B 64x32B (hi+lo); s encodes (nt, kt)
// ---------------------------------------------------------------------------
__device__ __forceinline__ void cp_stage(uint32_t sb, int m0, int s, int tid){
    int slot = s & 3;
    int kt = s & 31;
    int n0 = (s >> 5) << 6;
    uint32_t base = sb + slot*STAGE_SZ;
    int row = tid >> 1, c = tid & 1;
    size_t ka = (size_t)(m0 + row)*HH + kt*32 + c*16;
    cp16(base + row*32 + c*16, g_qa_hi + ka);
    cp16(base + OALO + row*32 + c*16, g_qa_lo + ka);
    if (tid < 128){
        size_t kb = (size_t)(n0 + row)*HH + kt*32 + c*16;
        cp16(base + OBHI + row*32 + c*16, g_qb_hi + kb);
    } else {
        int t2 = tid - 128;
        int r2 = t2 >> 1, c2 = t2 & 1;
        size_t kb = (size_t)(n0 + r2)*HH + kt*32 + c2*16;
        cp16(base + OBLO + r2*32 + c2*16, g_qb_lo + kb);
    }
    cp_commit();
}

// ---------------------------------------------------------------------------
// fused int8 GEMM (double-split) + tanh + v-dot
// CTA 128M x (16 x 64N); 8 warps (4M x 2N), warp tile 32x32, k32 stages.
// Flattened (nt,kt) pipeline: 512 stages, 4 buffers, no inter-nt drain.
// ---------------------------------------------------------------------------
__global__ void __launch_bounds__(256, 2)
gemm_score(const float* __restrict__ v){
    extern __shared__ __align__(128) char smem[];
    uint32_t sb = smem_u32(smem);
    const int tid  = threadIdx.x;
    const int lane = tid & 31;
    const int wid  = tid >> 5;
    const int wm   = wid & 3;       // 4 M-bands of 32
    const int wn   = wid >> 2;      // 2 N-bands of 32
    const int m0   = blockIdx.x * 128;

    float* red = (float*)(smem + O_RED);
    for (int i = tid; i < 128*17; i += 256) red[i] = 0.f;
    __syncthreads();

    const int r0 = wm*32 + (lane>>2);     // A row base (within 128)
    const int q8 = (lane&3)*8;            // stored-byte base within 32B row
    const int nbase = wn*32 + (lane>>2);  // B row base (within 64)

    int hh[2][4][4], cx[2][4][4];
    #pragma unroll
    for (int mf = 0; mf < 2; mf++)
        #pragma unroll
        for (int nb = 0; nb < 4; nb++)
            #pragma unroll
            for (int c = 0; c < 4; c++){ hh[mf][nb][c] = 0; cx[mf][nb][c] = 0; }

    cp_stage(sb, m0, 0, tid);
    cp_stage(sb, m0, 1, tid);
    cp_stage(sb, m0, 2, tid);

    for (int s = 0; s < 512; ++s){
        if (s < 509) cp_wait2(); else cp_wait0();
        __syncthreads();
        if (s + 3 < 512) cp_stage(sb, m0, s + 3, tid);

        const char* st = smem + (s&3)*STAGE_SZ;

        // B fragments: 4 n8-blocks x (hi, lo); each one LDS.64
        uint2 Bh[4], Bl[4];
        #pragma unroll
        for (int nb = 0; nb < 4; ++nb){
            Bh[nb] = *(const uint2*)(st + OBHI + (nbase + nb*8)*32 + q8);
            Bl[nb] = *(const uint2*)(st + OBLO + (nbase + nb*8)*32 + q8);
        }
        #pragma unroll
        for (int mf = 0; mf < 2; ++mf){
            uint2 AhL = *(const uint2*)(st + (r0 + mf*16    )*32 + q8);  // a0,a2 hi
            uint2 AhH = *(const uint2*)(st + (r0 + mf*16 + 8)*32 + q8);  // a1,a3 hi
            uint2 AlL = *(const uint2*)(st + OALO + (r0 + mf*16    )*32 + q8);
            uint2 AlH = *(const uint2*)(st + OALO + (r0 + mf*16 + 8)*32 + q8);
            #pragma unroll
            for (int nb = 0; nb < 4; ++nb){
                imma(hh[mf][nb], AhL.x, AhH.x, AhL.y, AhH.y, Bh[nb].x, Bh[nb].y);
                imma(cx[mf][nb], AhL.x, AhH.x, AhL.y, AhH.y, Bl[nb].x, Bl[nb].y);
                imma(cx[mf][nb], AlL.x, AlH.x, AlL.y, AlH.y, Bh[nb].x, Bh[nb].y);
            }
        }

        if ((s & 31) == 31){
            // epilogue for nt = s>>5 (N columns n0t..n0t+63)
            int n0t = (s >> 5) << 6;
            int npb = (n0t >> 1) + wn*16 + (lane&3);
            float2 vp[4], pstr[4][4];    // pstr[bg][nb]
            #pragma unroll
            for (int nb = 0; nb < 4; ++nb){
                int np = npb + nb*4;
                vp[nb] = *(const float2*)((const float*)v + np*2);
                #pragma unroll
                for (int bg = 0; bg < 4; ++bg){
                    int b = (bg&1)*8 + (bg>>1)*16 + (lane>>2);   // bg = mf*2+half -> b = mf*16+half*8+...
                    pstr[bg][nb] = __ldg(&g_pstP[np*BB + b]);
                }
            }
            #pragma unroll
            for (int mf = 0; mf < 2; ++mf){
                #pragma unroll
                for (int half = 0; half < 2; ++half){
                    int row = wm*32 + mf*16 + half*8 + (lane>>2);
                    int bg  = mf*2 + half;
                    float sacc = 0.f;
                    #pragma unroll
                    for (int nb = 0; nb < 4; ++nb){
                        float x0 = fmaf((float)hh[mf][nb][half*2+0], S1,
                                   fmaf((float)cx[mf][nb][half*2+0], S2, pstr[bg][nb].x));
                        float x1 = fmaf((float)hh[mf][nb][half*2+1], S1,
                                   fmaf((float)cx[mf][nb][half*2+1], S2, pstr[bg][nb].y));
                        float2 t = tanh2(x0, x1);
                        sacc = fmaf(vp[nb].x, t.x, fmaf(vp[nb].y, t.y, sacc));
                    }
                    red[row*17 + wn*4 + (lane&3)] += sacc;
                }
            }
            #pragma unroll
            for (int mf = 0; mf < 2; mf++)
                #pragma unroll
                for (int nb = 0; nb < 4; nb++)
                    #pragma unroll
                    for (int c = 0; c < 4; c++){ hh[mf][nb][c] = 0; cx[mf][nb][c] = 0; }
        }
    }

    __syncthreads();
    if (tid < 128){
        const float* r = red + tid*17;
        float sscore = 0.f;
        #pragma unroll
        for (int j = 0; j < 8; ++j) sscore += r[j];
        g_score[m0 + tid] = sscore;
    }
}

// ---------------------------------------------------------------------------
// softmax over L per batch column b; weights -> out + B*H, layout [l*B+b]
// ---------------------------------------------------------------------------
__global__ void softmax_kernel(float* __restrict__ out){
    __shared__ float sdata[256];
    int b = blockIdx.x;
    int tid = threadIdx.x;

    float mx = -1e30f;
    for (int l = tid; l < LL; l += 256) mx = fmaxf(mx, g_score[l*BB + b]);
    sdata[tid] = mx; __syncthreads();
    for (int s = 128; s > 0; s >>= 1){ if (tid < s) sdata[tid] = fmaxf(sdata[tid], sdata[tid+s]); __syncthreads(); }
    mx = sdata[0]; __syncthreads();

    float sum = 0.f;
    for (int l = tid; l < LL; l += 256) sum += __expf(g_score[l*BB + b] - mx);
    sdata[tid] = sum; __syncthreads();
    for (int s = 128; s > 0; s >>= 1){ if (tid < s) sdata[tid] += sdata[tid+s]; __syncthreads(); }
    float inv = 1.f / sdata[0];

    float* w = out + BB*HH;
    for (int l = tid; l < LL; l += 256)
        w[l*BB + b] = __expf(g_score[l*BB + b] - mx) * inv;
}

// ---------------------------------------------------------------------------
// context: 32-way L-split partials, then reduce; float4 over H
// ---------------------------------------------------------------------------
__global__ void ctx_part(const float* __restrict__ enc, const float* __restrict__ wts){
    int s = blockIdx.x;
    int b = blockIdx.y;
    int t = threadIdx.x;
    const float4* e = (const float4*)enc;
    float4 acc = make_float4(0.f, 0.f, 0.f, 0.f);
    int l0 = s * 64;
    #pragma unroll 4
    for (int l = 0; l < 64; ++l){
        float w = wts[(l0 + l)*BB + b];
        float4 x = e[((size_t)(l0 + l)*BB + b)*256 + t];
        acc.x += w*x.x; acc.y += w*x.y; acc.z += w*x.z; acc.w += w*x.w;
    }
    ((float4*)g_cpart)[((size_t)s*BB + b)*256 + t] = acc;
}
__global__ void ctx_reduce(float* __restrict__ out){
    int b = blockIdx.x;
    int t = threadIdx.x;
    float4 acc = make_float4(0.f, 0.f, 0.f, 0.f);
    #pragma unroll
    for (int s = 0; s < 32; ++s){
        float4 x = ((const float4*)g_cpart)[((size_t)s*BB + b)*256 + t];
        acc.x += x.x; acc.y += x.y; acc.z += x.z; acc.w += x.w;
    }
    ((float4*)out)[b*256 + t] = acc;
}

// ---------------------------------------------------------------------------
// launch: out = [context (B*H) | att_weights (L*B)]
// ---------------------------------------------------------------------------
extern "C" void kernel_launch(void* const* d_in, const int* in_sizes, int n_in,
                              void* d_out, int out_size) {
    const float* enc = (const float*)d_in[0];
    const float* lds = (const float*)d_in[1];   // state = first B*H floats
    const float* w1w = (const float*)d_in[2];
    const float* w1b = (const float*)d_in[3];
    const float* w2w = (const float*)d_in[4];
    const float* w2b = (const float*)d_in[5];
    const float* vw  = (const float*)d_in[6];
    // v_b cancels under softmax

    float* out = (float*)d_out;

    static bool attr_set = false;
    if (!attr_set){
        cudaFuncSetAttribute(gemm_score, cudaFuncAttributeMaxDynamicSharedMemorySize, SMEM_BYTES);
        attr_set = true;
    }

    uint8_t *qa_hi, *qa_lo, *qb_hi, *qb_lo;
    cudaGetSymbolAddress((void**)&qa_hi, g_qa_hi);
    cudaGetSymbolAddress((void**)&qa_lo, g_qa_lo);
    cudaGetSymbolAddress((void**)&qb_hi, g_qb_hi);
    cudaGetSymbolAddress((void**)&qb_lo, g_qb_lo);

    quant_kernel<<<MM*128/256, 256>>>(enc, qa_hi, qa_lo, INV_SA);
    quant_kernel<<<HH*128/256, 256>>>(w1w, qb_hi, qb_lo, INV_SB);
    pstT_kernel<<<(HH/2)*(BB/2)/8, 256>>>(lds, w2w, w1b, w2b);
    gemm_score<<<MM/128, 256, SMEM_BYTES>>>(vw);
    softmax_kernel<<<BB, 256>>>(out);
    ctx_part<<<dim3(32, BB), 256>>>(enc, out + BB*HH);
    ctx_reduce<<<BB, 256>>>(out);
}

// round 8
// speedup vs baseline: 4.0819x; 4.0819x over previous
#include <cuda_runtime.h>
#include <cuda_fp16.h>
#include <cstdint>

#define LL 2048
#define BB 32
#define HH 1024
#define MM (LL*BB)

// ---------------- device scratch ----------------
__device__ __half g_ah[(size_t)MM*HH];   // enc fp16, k-permuted within k16 windows
__device__ __half g_bh[(size_t)HH*HH];   // w1 fp16, same permutation
__device__ float2 g_pstP[(HH/2)*BB];     // (pst[2np][b], pst[2np+1][b]), bias folded
__device__ float g_score[MM];            // scores [l*B+b]
__device__ float g_cpart[32*BB*HH];      // context partials

// ---------------- PTX helpers ----------------
__device__ __forceinline__ uint32_t smem_u32(const void* p){
    uint32_t a;
    asm("{ .reg .u64 t; cvta.to.shared.u64 t, %1; cvt.u32.u64 %0, t; }" : "=r"(a) : "l"(p));
    return a;
}
__device__ __forceinline__ void cp16(uint32_t dst, const void* src){
    asm volatile("cp.async.ca.shared.global [%0], [%1], 16;" :: "r"(dst), "l"(src));
}
__device__ __forceinline__ void cp_commit(){ asm volatile("cp.async.commit_group;" ::: "memory"); }
__device__ __forceinline__ void cp_wait2(){ asm volatile("cp.async.wait_group 2;" ::: "memory"); }
__device__ __forceinline__ void cp_wait0(){ asm volatile("cp.async.wait_group 0;" ::: "memory"); }
__device__ __forceinline__ void mma_f16(float* c, uint32_t a0, uint32_t a1, uint32_t a2, uint32_t a3,
                                        uint32_t b0, uint32_t b1){
    asm volatile("mma.sync.aligned.m16n8k16.row.col.f32.f16.f16.f32 "
        "{%0,%1,%2,%3}, {%4,%5,%6,%7}, {%8,%9}, {%0,%1,%2,%3};"
        : "+f"(c[0]), "+f"(c[1]), "+f"(c[2]), "+f"(c[3])
        : "r"(a0), "r"(a1), "r"(a2), "r"(a3), "r"(b0), "r"(b1));
}
// pair tanh via f16x2 MUFU
__device__ __forceinline__ float2 tanh2(float x0, float x1){
    uint32_t h2, t2;
    asm("cvt.rn.f16x2.f32 %0, %1, %2;" : "=r"(h2) : "f"(x1), "f"(x0));
    asm("tanh.approx.f16x2 %0, %1;" : "=r"(t2) : "r"(h2));
    float r0, r1;
    asm("{.reg .b16 l, h;\n mov.b32 {l, h}, %2;\n cvt.f32.f16 %0, l;\n cvt.f32.f16 %1, h;}"
        : "=f"(r0), "=f"(r1) : "r"(t2));
    return make_float2(r0, r1);
}

// ---------------- SMEM layout ----------------
// stage (k16): A 128 rows x 32B + B 128 rows x 32B = 8192 B; 4 stages
#define STAGE_SZ 8192
#define OB       4096
#define O_RED    32768
#define SMEM_BYTES 41472     // 4*8192 + 128*17*4

// ---------------------------------------------------------------------------
// fp32 -> fp16, k-permuted within each k16 window:
// stored pos 4q+{0,1,2,3} <- orig k {2q, 2q+1, 2q+8, 2q+9}  (q = 0..3)
// Same permutation on A and B => sum over k unchanged.
// One thread per (row, k16 window): read 16 floats, write 32 bytes.
// ---------------------------------------------------------------------------
__global__ void conv_half(const float* __restrict__ src, __half* __restrict__ dst){
    int t = blockIdx.x * 256 + threadIdx.x;
    int w = t & 63;             // k16 window
    int m = t >> 6;             // row
    const float* p = src + (size_t)m*HH + w*16;
    float4 x0 = *(const float4*)(p);
    float4 x1 = *(const float4*)(p + 4);
    float4 x2 = *(const float4*)(p + 8);
    float4 x3 = *(const float4*)(p + 12);
    float in[16] = {x0.x,x0.y,x0.z,x0.w, x1.x,x1.y,x1.z,x1.w,
                    x2.x,x2.y,x2.z,x2.w, x3.x,x3.y,x3.z,x3.w};
    uint32_t o[8];
    #pragma unroll
    for (int q = 0; q < 4; ++q){
        __half2 lo = __floats2half2_rn(in[2*q],     in[2*q + 1]);
        __half2 hi = __floats2half2_rn(in[2*q + 8], in[2*q + 9]);
        o[2*q]     = *(uint32_t*)&lo;
        o[2*q + 1] = *(uint32_t*)&hi;
    }
    uint4* d = (uint4*)(dst + (size_t)m*HH + w*16);
    d[0] = make_uint4(o[0], o[1], o[2], o[3]);
    d[1] = make_uint4(o[4], o[5], o[6], o[7]);
}

// ---------------------------------------------------------------------------
// pstP[np*32+b] = (pst[2np][b], pst[2np+1][b]); exact fp32
// ---------------------------------------------------------------------------
__global__ void pstT_kernel(const float* __restrict__ state, const float* __restrict__ w2,
                            const float* __restrict__ w1b, const float* __restrict__ w2b){
    int gw = (blockIdx.x * blockDim.x + threadIdx.x) >> 5;
    int lane = threadIdx.x & 31;
    if (gw >= (HH/2)*(BB/2)) return;
    int np = gw >> 4;
    int b0 = (gw & 15) * 2;
    int n0 = np * 2;
    const float* w0 = w2 + (size_t)n0 * HH;
    const float* w1r = w2 + (size_t)(n0+1) * HH;
    const float* s0 = state + b0*HH;
    const float* s1 = state + (b0+1)*HH;
    float a00=0.f, a01=0.f, a10=0.f, a11=0.f;
    #pragma unroll 4
    for (int h = lane; h < HH; h += 32){
        float x0 = s0[h], x1 = s1[h];
        float u = w0[h], w = w1r[h];
        a00 += u*x0; a01 += u*x1;
        a10 += w*x0; a11 += w*x1;
    }
    #pragma unroll
    for (int o = 16; o; o >>= 1){
        a00 += __shfl_xor_sync(~0u, a00, o);
        a01 += __shfl_xor_sync(~0u, a01, o);
        a10 += __shfl_xor_sync(~0u, a10, o);
        a11 += __shfl_xor_sync(~0u, a11, o);
    }
    if (lane == 0){
        float bias0 = w1b[n0] + w2b[n0];
        float bias1 = w1b[n0+1] + w2b[n0+1];
        g_pstP[np*BB + b0]   = make_float2(a00 + bias0, a10 + bias1);
        g_pstP[np*BB + b0+1] = make_float2(a01 + bias0, a11 + bias1);
    }
}

// ---------------------------------------------------------------------------
// cp.async one stage: A 128x32B + B 128x32B; s encodes (nt, kt)
// ---------------------------------------------------------------------------
__device__ __forceinline__ void cp_stage(uint32_t sb, int m0, int s, int tid){
    int slot = s & 3;
    int kt = s & 63;
    int n0 = (s >> 6) << 7;
    uint32_t base = sb + slot*STAGE_SZ;
    int row = tid >> 1, h = tid & 1;
    cp16(base + row*32 + h*16, g_ah + (size_t)(m0 + row)*HH + kt*16 + h*8);
    cp16(base + OB + row*32 + h*16, g_bh + (size_t)(n0 + row)*HH + kt*16 + h*8);
    cp_commit();
}

// ---------------------------------------------------------------------------
// fused fp16 GEMM + tanh + v-dot
// CTA 128M x (8 x 128N); 8 warps (2M x 4N), warp tile 64x32, k16 stages.
// Flattened (nt,kt) pipeline: 512 stages, 4 buffers, single sync per stage.
// Fragments via k-permuted layout: one LDS.64 per (row-half / col) per kt.
// ---------------------------------------------------------------------------
__global__ void __launch_bounds__(256, 2)
gemm_score(const float* __restrict__ v){
    extern __shared__ __align__(128) char smem[];
    uint32_t sb = smem_u32(smem);
    const int tid  = threadIdx.x;
    const int lane = tid & 31;
    const int wid  = tid >> 5;
    const int wm   = wid & 1;       // 2 M-bands of 64
    const int wn   = wid >> 1;      // 4 N-bands of 32
    const int m0   = blockIdx.x * 128;

    float* red = (float*)(smem + O_RED);
    for (int i = tid; i < 128*17; i += 256) red[i] = 0.f;
    __syncthreads();

    const int r0  = wm*64 + (lane>>2);    // A row base
    const int t8  = (lane&3)*8;           // byte offset of lane's 4 halves
    const int nb0 = wn*32 + (lane>>2);    // B row base

    float acc[4][4][4];
    #pragma unroll
    for (int a = 0; a < 4; a++)
        #pragma unroll
        for (int b = 0; b < 4; b++)
            #pragma unroll
            for (int c = 0; c < 4; c++) acc[a][b][c] = 0.f;

    cp_stage(sb, m0, 0, tid);
    cp_stage(sb, m0, 1, tid);
    cp_stage(sb, m0, 2, tid);

    for (int s = 0; s < 512; ++s){
        if (s < 509) cp_wait2(); else cp_wait0();
        __syncthreads();
        if (s + 3 < 512) cp_stage(sb, m0, s + 3, tid);

        const char* st = smem + (s&3)*STAGE_SZ;

        uint2 Bu[4];
        #pragma unroll
        for (int nf = 0; nf < 4; ++nf)
            Bu[nf] = *(const uint2*)(st + OB + (nb0 + nf*8)*32 + t8);

        #pragma unroll
        for (int mf = 0; mf < 4; ++mf){
            uint2 a_lo = *(const uint2*)(st + (r0 + mf*16    )*32 + t8);
            uint2 a_hi = *(const uint2*)(st + (r0 + mf*16 + 8)*32 + t8);
            #pragma unroll
            for (int nf = 0; nf < 4; ++nf)
                mma_f16(acc[mf][nf], a_lo.x, a_hi.x, a_lo.y, a_hi.y, Bu[nf].x, Bu[nf].y);
        }

        if ((s & 63) == 63){
            // epilogue for nt = s>>6 (N columns n0t..n0t+127)
            int n0t = (s >> 6) << 7;
            int npb = (n0t >> 1) + wn*16 + (lane&3);   // wn*32/2
            float2 vp[4], pstr[4][4];                   // pstr[bg][nf]
            #pragma unroll
            for (int nf = 0; nf < 4; ++nf){
                int np = npb + nf*4;
                vp[nf] = *(const float2*)(v + np*2);
                #pragma unroll
                for (int bg = 0; bg < 4; ++bg){
                    int b = (lane>>2) + bg*8;
                    pstr[bg][nf] = __ldg(&g_pstP[np*BB + b]);
                }
            }
            #pragma unroll
            for (int mf = 0; mf < 4; ++mf){
                #pragma unroll
                for (int half = 0; half < 2; ++half){
                    int row = wm*64 + mf*16 + (lane>>2) + half*8;
                    int bg  = (mf&1)*2 + half;
                    float sacc = 0.f;
                    #pragma unroll
                    for (int nf = 0; nf < 4; ++nf){
                        float x0 = acc[mf][nf][half*2 + 0] + pstr[bg][nf].x;
                        float x1 = acc[mf][nf][half*2 + 1] + pstr[bg][nf].y;
                        float2 t = tanh2(x0, x1);
                        sacc = fmaf(vp[nf].x, t.x, fmaf(vp[nf].y, t.y, sacc));
                    }
                    red[row*17 + wn*4 + (lane&3)] += sacc;
                }
            }
            #pragma unroll
            for (int a = 0; a < 4; a++)
                #pragma unroll
                for (int b = 0; b < 4; b++)
                    #pragma unroll
                    for (int c = 0; c < 4; c++) acc[a][b][c] = 0.f;
        }
    }

    __syncthreads();
    if (tid < 128){
        const float* r = red + tid*17;
        float s = 0.f;
        #pragma unroll
        for (int j = 0; j < 16; ++j) s += r[j];
        g_score[m0 + tid] = s;
    }
}

// ---------------------------------------------------------------------------
// softmax over L per batch column b; weights -> out + B*H, layout [l*B+b]
// ---------------------------------------------------------------------------
__global__ void softmax_kernel(float* __restrict__ out){
    __shared__ float sdata[256];
    int b = blockIdx.x;
    int tid = threadIdx.x;

    float mx = -1e30f;
    for (int l = tid; l < LL; l += 256) mx = fmaxf(mx, g_score[l*BB + b]);
    sdata[tid] = mx; __syncthreads();
    for (int s = 128; s > 0; s >>= 1){ if (tid < s) sdata[tid] = fmaxf(sdata[tid], sdata[tid+s]); __syncthreads(); }
    mx = sdata[0]; __syncthreads();

    float sum = 0.f;
    for (int l = tid; l < LL; l += 256) sum += __expf(g_score[l*BB + b] - mx);
    sdata[tid] = sum; __syncthreads();
    for (int s = 128; s > 0; s >>= 1){ if (tid < s) sdata[tid] += sdata[tid+s]; __syncthreads(); }
    float inv = 1.f / sdata[0];

    float* w = out + BB*HH;
    for (int l = tid; l < LL; l += 256)
        w[l*BB + b] = __expf(g_score[l*BB + b] - mx) * inv;
}

// ---------------------------------------------------------------------------
// context: 32-way L-split partials, then reduce; float4 over H
// ---------------------------------------------------------------------------
__global__ void ctx_part(const float* __restrict__ enc, const float* __restrict__ wts){
    int s = blockIdx.x;
    int b = blockIdx.y;
    int t = threadIdx.x;
    const float4* e = (const float4*)enc;
    float4 acc = make_float4(0.f, 0.f, 0.f, 0.f);
    int l0 = s * 64;
    #pragma unroll 4
    for (int l = 0; l < 64; ++l){
        float w = wts[(l0 + l)*BB + b];
        float4 x = e[((size_t)(l0 + l)*BB + b)*256 + t];
        acc.x += w*x.x; acc.y += w*x.y; acc.z += w*x.z; acc.w += w*x.w;
    }
    ((float4*)g_cpart)[((size_t)s*BB + b)*256 + t] = acc;
}
__global__ void ctx_reduce(float* __restrict__ out){
    int b = blockIdx.x;
    int t = threadIdx.x;
    float4 acc = make_float4(0.f, 0.f, 0.f, 0.f);
    #pragma unroll
    for (int s = 0; s < 32; ++s){
        float4 x = ((const float4*)g_cpart)[((size_t)s*BB + b)*256 + t];
        acc.x += x.x; acc.y += x.y; acc.z += x.z; acc.w += x.w;
    }
    ((float4*)out)[b*256 + t] = acc;
}

// ---------------------------------------------------------------------------
// launch: out = [context (B*H) | att_weights (L*B)]
// ---------------------------------------------------------------------------
extern "C" void kernel_launch(void* const* d_in, const int* in_sizes, int n_in,
                              void* d_out, int out_size) {
    const float* enc = (const float*)d_in[0];
    const float* lds = (const float*)d_in[1];   // state = first B*H floats
    const float* w1w = (const float*)d_in[2];
    const float* w1b = (const float*)d_in[3];
    const float* w2w = (const float*)d_in[4];
    const float* w2b = (const float*)d_in[5];
    const float* vw  = (const float*)d_in[6];
    // v_b cancels under softmax

    float* out = (float*)d_out;

    static bool attr_set = false;
    if (!attr_set){
        cudaFuncSetAttribute(gemm_score, cudaFuncAttributeMaxDynamicSharedMemorySize, SMEM_BYTES);
        attr_set = true;
    }

    __half *ah, *bh;
    cudaGetSymbolAddress((void**)&ah, g_ah);
    cudaGetSymbolAddress((void**)&bh, g_bh);

    conv_half<<<MM*64/256, 256>>>(enc, ah);
    conv_half<<<HH*64/256, 256>>>(w1w, bh);
    pstT_kernel<<<(HH/2)*(BB/2)/8, 256>>>(lds, w2w, w1b, w2b);
    gemm_score<<<MM/128, 256, SMEM_BYTES>>>(vw);
    softmax_kernel<<<BB, 256>>>(out);
    ctx_part<<<dim3(32, BB), 256>>>(enc, out + BB*HH);
    ctx_reduce<<<BB, 256>>>(out);
}

// round 9
// speedup vs baseline: 4.1271x; 1.0111x over previous
#include <cuda_runtime.h>
#include <cuda_fp16.h>
#include <cstdint>

#define LL 2048
#define BB 32
#define HH 1024
#define MM (LL*BB)

// ---------------- device scratch ----------------
__device__ __half g_ah[(size_t)MM*HH];   // enc fp16, k-permuted within k16 windows
__device__ __half g_bh[(size_t)HH*HH];   // w1 fp16, same permutation
__device__ float2 g_pstP[(HH/2)*BB];     // (pst[2np][b], pst[2np+1][b]), bias folded
__device__ float g_score[MM];            // scores [l*B+b]
__device__ float g_cpart[32*BB*HH];      // context partials

// ---------------- PTX helpers ----------------
__device__ __forceinline__ uint32_t smem_u32(const void* p){
    uint32_t a;
    asm("{ .reg .u64 t; cvta.to.shared.u64 t, %1; cvt.u32.u64 %0, t; }" : "=r"(a) : "l"(p));
    return a;
}
__device__ __forceinline__ void cp16(uint32_t dst, const void* src){
    asm volatile("cp.async.ca.shared.global [%0], [%1], 16;" :: "r"(dst), "l"(src));
}
__device__ __forceinline__ void cp_commit(){ asm volatile("cp.async.commit_group;" ::: "memory"); }
__device__ __forceinline__ void cp_wait2(){ asm volatile("cp.async.wait_group 2;" ::: "memory"); }
__device__ __forceinline__ void cp_wait0(){ asm volatile("cp.async.wait_group 0;" ::: "memory"); }
__device__ __forceinline__ void mma_f16(float* c, uint32_t a0, uint32_t a1, uint32_t a2, uint32_t a3,
                                        uint32_t b0, uint32_t b1){
    asm volatile("mma.sync.aligned.m16n8k16.row.col.f32.f16.f16.f32 "
        "{%0,%1,%2,%3}, {%4,%5,%6,%7}, {%8,%9}, {%0,%1,%2,%3};"
        : "+f"(c[0]), "+f"(c[1]), "+f"(c[2]), "+f"(c[3])
        : "r"(a0), "r"(a1), "r"(a2), "r"(a3), "r"(b0), "r"(b1));
}
// pair tanh via f16x2 MUFU
__device__ __forceinline__ float2 tanh2(float x0, float x1){
    uint32_t h2, t2;
    asm("cvt.rn.f16x2.f32 %0, %1, %2;" : "=r"(h2) : "f"(x1), "f"(x0));
    asm("tanh.approx.f16x2 %0, %1;" : "=r"(t2) : "r"(h2));
    float r0, r1;
    asm("{.reg .b16 l, h;\n mov.b32 {l, h}, %2;\n cvt.f32.f16 %0, l;\n cvt.f32.f16 %1, h;}"
        : "=f"(r0), "=f"(r1) : "r"(t2));
    return make_float2(r0, r1);
}

// ---------------- SMEM layout ----------------
// k32 stage = [A0 4K][A1 4K][B0 4K][B1 4K] = 16384 B; sub-tiles keep 32B rows
// (exact R8 conflict-free phase layout). 4 stages.
#define STAGE_SZ 16384
#define OB       8192
#define O_RED    65536
#define SMEM_BYTES 74240     // 4*16384 + 128*17*4

// ---------------------------------------------------------------------------
// fp32 -> fp16, k-permuted within each k16 window:
// stored pos 4q+{0,1,2,3} <- orig k {2q, 2q+1, 2q+8, 2q+9}  (q = 0..3)
// Same permutation on A and B => sum over k unchanged.
// ---------------------------------------------------------------------------
__global__ void conv_half(const float* __restrict__ src, __half* __restrict__ dst){
    int t = blockIdx.x * 256 + threadIdx.x;
    int w = t & 63;             // k16 window
    int m = t >> 6;             // row
    const float* p = src + (size_t)m*HH + w*16;
    float4 x0 = *(const float4*)(p);
    float4 x1 = *(const float4*)(p + 4);
    float4 x2 = *(const float4*)(p + 8);
    float4 x3 = *(const float4*)(p + 12);
    float in[16] = {x0.x,x0.y,x0.z,x0.w, x1.x,x1.y,x1.z,x1.w,
                    x2.x,x2.y,x2.z,x2.w, x3.x,x3.y,x3.z,x3.w};
    uint32_t o[8];
    #pragma unroll
    for (int q = 0; q < 4; ++q){
        __half2 lo = __floats2half2_rn(in[2*q],     in[2*q + 1]);
        __half2 hi = __floats2half2_rn(in[2*q + 8], in[2*q + 9]);
        o[2*q]     = *(uint32_t*)&lo;
        o[2*q + 1] = *(uint32_t*)&hi;
    }
    uint4* d = (uint4*)(dst + (size_t)m*HH + w*16);
    d[0] = make_uint4(o[0], o[1], o[2], o[3]);
    d[1] = make_uint4(o[4], o[5], o[6], o[7]);
}

// ---------------------------------------------------------------------------
// pstP[np*32+b] = (pst[2np][b], pst[2np+1][b]); exact fp32
// ---------------------------------------------------------------------------
__global__ void pstT_kernel(const float* __restrict__ state, const float* __restrict__ w2,
                            const float* __restrict__ w1b, const float* __restrict__ w2b){
    int gw = (blockIdx.x * blockDim.x + threadIdx.x) >> 5;
    int lane = threadIdx.x & 31;
    if (gw >= (HH/2)*(BB/2)) return;
    int np = gw >> 4;
    int b0 = (gw & 15) * 2;
    int n0 = np * 2;
    const float* w0 = w2 + (size_t)n0 * HH;
    const float* w1r = w2 + (size_t)(n0+1) * HH;
    const float* s0 = state + b0*HH;
    const float* s1 = state + (b0+1)*HH;
    float a00=0.f, a01=0.f, a10=0.f, a11=0.f;
    #pragma unroll 4
    for (int h = lane; h < HH; h += 32){
        float x0 = s0[h], x1 = s1[h];
        float u = w0[h], w = w1r[h];
        a00 += u*x0; a01 += u*x1;
        a10 += w*x0; a11 += w*x1;
    }
    #pragma unroll
    for (int o = 16; o; o >>= 1){
        a00 += __shfl_xor_sync(~0u, a00, o);
        a01 += __shfl_xor_sync(~0u, a01, o);
        a10 += __shfl_xor_sync(~0u, a10, o);
        a11 += __shfl_xor_sync(~0u, a11, o);
    }
    if (lane == 0){
        float bias0 = w1b[n0] + w2b[n0];
        float bias1 = w1b[n0+1] + w2b[n0+1];
        g_pstP[np*BB + b0]   = make_float2(a00 + bias0, a10 + bias1);
        g_pstP[np*BB + b0+1] = make_float2(a01 + bias0, a11 + bias1);
    }
}

// ---------------------------------------------------------------------------
// cp.async one k32 stage: A 128x64B + B 128x64B as 2 k16 sub-tiles each.
// s encodes (nt, kt32): kt32 = s & 31, n0 = (s>>5)*128.
// Each thread: 4 cp16 (A sub0, A sub1, B sub0, B sub1), one commit.
// ---------------------------------------------------------------------------
__device__ __forceinline__ void cp_stage(uint32_t sb, int m0, int s, int tid){
    int slot = s & 3;
    int kt = s & 31;
    int n0 = (s >> 5) << 7;
    uint32_t base = sb + slot*STAGE_SZ;
    int row = tid >> 1, c = tid & 1;
    const __half* asrc = g_ah + (size_t)(m0 + row)*HH + kt*32 + c*8;
    const __half* bsrc = g_bh + (size_t)(n0 + row)*HH + kt*32 + c*8;
    uint32_t adst = base + row*32 + c*16;
    uint32_t bdst = base + OB + row*32 + c*16;
    cp16(adst,        asrc);
    cp16(adst + 4096, asrc + 16);
    cp16(bdst,        bsrc);
    cp16(bdst + 4096, bsrc + 16);
    cp_commit();
}

// ---------------------------------------------------------------------------
// fused fp16 GEMM + tanh + v-dot
// CTA 128M x (8 x 128N); 8 warps (2M x 4N), warp tile 64x32, k32 macro-stages.
// 256 stages total, one sync + one commit per 32 warp-MMAs.
// ---------------------------------------------------------------------------
__global__ void __launch_bounds__(256, 2)
gemm_score(const float* __restrict__ v){
    extern __shared__ __align__(128) char smem[];
    uint32_t sb = smem_u32(smem);
    const int tid  = threadIdx.x;
    const int lane = tid & 31;
    const int wid  = tid >> 5;
    const int wm   = wid & 1;       // 2 M-bands of 64
    const int wn   = wid >> 1;      // 4 N-bands of 32
    const int m0   = blockIdx.x * 128;

    float* red = (float*)(smem + O_RED);
    for (int i = tid; i < 128*17; i += 256) red[i] = 0.f;
    __syncthreads();

    const int r0  = wm*64 + (lane>>2);    // A row base
    const int t8  = (lane&3)*8;           // byte offset of lane's 4 halves
    const int nb0 = wn*32 + (lane>>2);    // B row base

    float acc[4][4][4];
    #pragma unroll
    for (int a = 0; a < 4; a++)
        #pragma unroll
        for (int b = 0; b < 4; b++)
            #pragma unroll
            for (int c = 0; c < 4; c++) acc[a][b][c] = 0.f;

    cp_stage(sb, m0, 0, tid);
    cp_stage(sb, m0, 1, tid);
    cp_stage(sb, m0, 2, tid);

    for (int s = 0; s < 256; ++s){
        if (s < 253) cp_wait2(); else cp_wait0();
        __syncthreads();
        if (s + 3 < 256) cp_stage(sb, m0, s + 3, tid);

        const char* st = smem + (s&3)*STAGE_SZ;

        #pragma unroll
        for (int h = 0; h < 2; ++h){
            const char* sA = st + h*4096;
            const char* sB = st + OB + h*4096;

            // batch all loads first (MLP), then all MMAs
            uint2 Bu[4];
            #pragma unroll
            for (int nf = 0; nf < 4; ++nf)
                Bu[nf] = *(const uint2*)(sB + (nb0 + nf*8)*32 + t8);

            uint2 Alo[4], Ahi[4];
            #pragma unroll
            for (int mf = 0; mf < 4; ++mf){
                Alo[mf] = *(const uint2*)(sA + (r0 + mf*16    )*32 + t8);
                Ahi[mf] = *(const uint2*)(sA + (r0 + mf*16 + 8)*32 + t8);
            }

            #pragma unroll
            for (int mf = 0; mf < 4; ++mf)
                #pragma unroll
                for (int nf = 0; nf < 4; ++nf)
                    mma_f16(acc[mf][nf], Alo[mf].x, Ahi[mf].x, Alo[mf].y, Ahi[mf].y,
                            Bu[nf].x, Bu[nf].y);
        }

        if ((s & 31) == 31){
            // epilogue for nt = s>>5 (N columns n0t..n0t+127)
            int n0t = (s >> 5) << 7;
            int npb = (n0t >> 1) + wn*16 + (lane&3);
            float2 vp[4], pstr[4][4];                   // pstr[bg][nf]
            #pragma unroll
            for (int nf = 0; nf < 4; ++nf){
                int np = npb + nf*4;
                vp[nf] = *(const float2*)(v + np*2);
                #pragma unroll
                for (int bg = 0; bg < 4; ++bg){
                    int b = (lane>>2) + bg*8;
                    pstr[bg][nf] = __ldg(&g_pstP[np*BB + b]);
                }
            }
            #pragma unroll
            for (int mf = 0; mf < 4; ++mf){
                #pragma unroll
                for (int half = 0; half < 2; ++half){
                    int row = wm*64 + mf*16 + (lane>>2) + half*8;
                    int bg  = (mf&1)*2 + half;
                    float sacc = 0.f;
                    #pragma unroll
                    for (int nf = 0; nf < 4; ++nf){
                        float x0 = acc[mf][nf][half*2 + 0] + pstr[bg][nf].x;
                        float x1 = acc[mf][nf][half*2 + 1] + pstr[bg][nf].y;
                        float2 t = tanh2(x0, x1);
                        sacc = fmaf(vp[nf].x, t.x, fmaf(vp[nf].y, t.y, sacc));
                    }
                    red[row*17 + wn*4 + (lane&3)] += sacc;
                }
            }
            #pragma unroll
            for (int a = 0; a < 4; a++)
                #pragma unroll
                for (int b = 0; b < 4; b++)
                    #pragma unroll
                    for (int c = 0; c < 4; c++) acc[a][b][c] = 0.f;
        }
    }

    __syncthreads();
    if (tid < 128){
        const float* r = red + tid*17;
        float s = 0.f;
        #pragma unroll
        for (int j = 0; j < 16; ++j) s += r[j];
        g_score[m0 + tid] = s;
    }
}

// ---------------------------------------------------------------------------
// softmax over L per batch column b; weights -> out + B*H, layout [l*B+b]
// ---------------------------------------------------------------------------
__global__ void softmax_kernel(float* __restrict__ out){
    __shared__ float sdata[256];
    int b = blockIdx.x;
    int tid = threadIdx.x;

    float mx = -1e30f;
    for (int l = tid; l < LL; l += 256) mx = fmaxf(mx, g_score[l*BB + b]);
    sdata[tid] = mx; __syncthreads();
    for (int s = 128; s > 0; s >>= 1){ if (tid < s) sdata[tid] = fmaxf(sdata[tid], sdata[tid+s]); __syncthreads(); }
    mx = sdata[0]; __syncthreads();

    float sum = 0.f;
    for (int l = tid; l < LL; l += 256) sum += __expf(g_score[l*BB + b] - mx);
    sdata[tid] = sum; __syncthreads();
    for (int s = 128; s > 0; s >>= 1){ if (tid < s) sdata[tid] += sdata[tid+s]; __syncthreads(); }
    float inv = 1.f / sdata[0];

    float* w = out + BB*HH;
    for (int l = tid; l < LL; l += 256)
        w[l*BB + b] = __expf(g_score[l*BB + b] - mx) * inv;
}

// ---------------------------------------------------------------------------
// context: 32-way L-split partials, then reduce; float4 over H
// ---------------------------------------------------------------------------
__global__ void ctx_part(const float* __restrict__ enc, const float* __restrict__ wts){
    int s = blockIdx.x;
    int b = blockIdx.y;
    int t = threadIdx.x;
    const float4* e = (const float4*)enc;
    float4 acc = make_float4(0.f, 0.f, 0.f, 0.f);
    int l0 = s * 64;
    #pragma unroll 4
    for (int l = 0; l < 64; ++l){
        float w = wts[(l0 + l)*BB + b];
        float4 x = e[((size_t)(l0 + l)*BB + b)*256 + t];
        acc.x += w*x.x; acc.y += w*x.y; acc.z += w*x.z; acc.w += w*x.w;
    }
    ((float4*)g_cpart)[((size_t)s*BB + b)*256 + t] = acc;
}
__global__ void ctx_reduce(float* __restrict__ out){
    int b = blockIdx.x;
    int t = threadIdx.x;
    float4 acc = make_float4(0.f, 0.f, 0.f, 0.f);
    #pragma unroll
    for (int s = 0; s < 32; ++s){
        float4 x = ((const float4*)g_cpart)[((size_t)s*BB + b)*256 + t];
        acc.x += x.x; acc.y += x.y; acc.z += x.z; acc.w += x.w;
    }
    ((float4*)out)[b*256 + t] = acc;
}

// ---------------------------------------------------------------------------
// launch: out = [context (B*H) | att_weights (L*B)]
// ---------------------------------------------------------------------------
extern "C" void kernel_launch(void* const* d_in, const int* in_sizes, int n_in,
                              void* d_out, int out_size) {
    const float* enc = (const float*)d_in[0];
    const float* lds = (const float*)d_in[1];   // state = first B*H floats
    const float* w1w = (const float*)d_in[2];
    const float* w1b = (const float*)d_in[3];
    const float* w2w = (const float*)d_in[4];
    const float* w2b = (const float*)d_in[5];
    const float* vw  = (const float*)d_in[6];
    // v_b cancels under softmax

    float* out = (float*)d_out;

    static bool attr_set = false;
    if (!attr_set){
        cudaFuncSetAttribute(gemm_score, cudaFuncAttributeMaxDynamicSharedMemorySize, SMEM_BYTES);
        attr_set = true;
    }

    __half *ah, *bh;
    cudaGetSymbolAddress((void**)&ah, g_ah);
    cudaGetSymbolAddress((void**)&bh, g_bh);

    conv_half<<<MM*64/256, 256>>>(enc, ah);
    conv_half<<<HH*64/256, 256>>>(w1w, bh);
    pstT_kernel<<<(HH/2)*(BB/2)/8, 256>>>(lds, w2w, w1b, w2b);
    gemm_score<<<MM/128, 256, SMEM_BYTES>>>(vw);
    softmax_kernel<<<BB, 256>>>(out);
    ctx_part<<<dim3(32, BB), 256>>>(enc, out + BB*HH);
    ctx_reduce<<<BB, 256>>>(out);
}